// round 14
// baseline (speedup 1.0000x reference)
#include <cuda_runtime.h>
#include <cuda_bf16.h>
#include <cstdint>
#include <math.h>

#define N_ROWS 32768
#define DIM    512
#define NQ     8
#define NK     4096
#define THRESH 6e-4f

// fast kernel geometry (round-10 proven, FROZEN)
#define BM 128
#define BN 128
#define BK 64
#define CTILES (NK / BN)   // 32
#define KCH    (DIM / BK)  // 8

#define SA_OFF   0
#define SB_OFF   32768
#define RED_OFF  65536
#define SMEM_FAST (65536 + 512 * 4 * 3)  // 71680

// Scratch (__device__ globals, referenced by name in kernels only)
__device__ float g_res[(size_t)N_ROWS * DIM];
__device__ float g_bnorm_all[(size_t)NQ * NK * DIM];   // normalized codebooks, fp32
__device__ float g_rnorm[N_ROWS];
__device__ float g_cnorm_all[NQ * NK];
__device__ int   g_ids[N_ROWS];
__device__ int   g_flag_count;
__device__ int   g_flag_rows[N_ROWS];
__device__ unsigned long long g_pkey[N_ROWS];          // packed (sim,~idx) per slot
__device__ uint4 g_ahi[(size_t)N_ROWS * DIM / 8];      // bf16 residual
__device__ uint4 g_bhi_all[(size_t)NQ * NK * DIM / 8]; // bf16 codebooks
__device__ float g_aflag[(size_t)N_ROWS * DIM];        // normalized flagged rows

// ---------------------------------------------------------------------------
// helpers
// ---------------------------------------------------------------------------
__device__ __forceinline__ uint32_t smem_u32(const void* p) {
    uint32_t a;
    asm("{ .reg .u64 t; cvta.to.shared.u64 t, %1; cvt.u32.u64 %0, t; }"
        : "=r"(a) : "l"(p));
    return a;
}
__device__ __forceinline__ unsigned long long packf2(float lo, float hi) {
    unsigned long long r;
    asm("mov.b64 %0, {%1, %2};" : "=l"(r) : "f"(lo), "f"(hi));
    return r;
}
__device__ __forceinline__ void fmaf2(unsigned long long& d,
                                      unsigned long long a, unsigned long long b) {
    asm("fma.rn.f32x2 %0, %1, %2, %0;" : "+l"(d) : "l"(a), "l"(b));
}
__device__ __forceinline__ void unpackf2(unsigned long long p, float& lo, float& hi) {
    asm("mov.b64 {%0, %1}, %2;" : "=f"(lo), "=f"(hi) : "l"(p));
}
__device__ __forceinline__ unsigned bf2u(float x, float y) {
    __nv_bfloat162 v = __floats2bfloat162_rn(x, y);
    return *(unsigned*)&v;
}
// monotonic float->uint map; key orders by (sim asc, idx desc) so that
// atomicMax picks (max sim, min idx) — exact jnp.argmax tie semantics.
__device__ __forceinline__ unsigned long long mkkey(float f, int idx) {
    unsigned u = __float_as_uint(f);
    u = (u & 0x80000000u) ? ~u : (u | 0x80000000u);
    return ((unsigned long long)u << 32) | (unsigned)(~idx);
}
__device__ __forceinline__ void cp16(uint32_t dst, const void* src) {
    asm volatile("cp.async.cg.shared.global [%0], [%1], 16;"
                 :: "r"(dst), "l"(src));
}
#define CP_COMMIT() asm volatile("cp.async.commit_group;" ::: "memory")
#define CP_WAIT(n)  asm volatile("cp.async.wait_group %0;" :: "n"(n) : "memory")
__device__ __forceinline__ void ldsm4(unsigned r[4], uint32_t addr) {
    asm volatile("ldmatrix.sync.aligned.m8n8.x4.shared.b16 {%0,%1,%2,%3}, [%4];"
                 : "=r"(r[0]), "=r"(r[1]), "=r"(r[2]), "=r"(r[3]) : "r"(addr));
}
__device__ __forceinline__ void mma16816(float c[4], const unsigned a[4],
                                         unsigned b0, unsigned b1) {
    asm volatile(
        "mma.sync.aligned.m16n8k16.row.col.f32.bf16.bf16.f32 "
        "{%0,%1,%2,%3}, {%4,%5,%6,%7}, {%8,%9}, {%0,%1,%2,%3};"
        : "+f"(c[0]), "+f"(c[1]), "+f"(c[2]), "+f"(c[3])
        : "r"(a[0]), "r"(a[1]), "r"(a[2]), "r"(a[3]), "r"(b0), "r"(b1));
}
#define SWZ128(bo) ((bo) ^ (((bo) >> 3) & 0x70))

// ---------------------------------------------------------------------------
// init: res = x, hard = 0
// ---------------------------------------------------------------------------
__global__ __launch_bounds__(256) void init_kernel(const float* __restrict__ x,
                                                   float* __restrict__ hard) {
    if (blockIdx.x == 0 && threadIdx.x == 0) g_flag_count = 0;
    size_t i = ((size_t)blockIdx.x * 256 + threadIdx.x) * 4;
    float4 v = *(const float4*)(x + i);
    *(float4*)(g_res + i) = v;
    *(float4*)(hard + i) = make_float4(0.f, 0.f, 0.f, 0.f);
}

// ---------------------------------------------------------------------------
// Row L2 norm, STRICT SEQUENTIAL fp32 order, coalesced via smem staging.
// ---------------------------------------------------------------------------
__device__ __forceinline__ void seq_norm_block(const float* __restrict__ src,
                                               float* __restrict__ dst,
                                               size_t row0) {
    __shared__ float s[64][65];
    const int tid = threadIdx.x;
    float acc = 0.f;
    for (int ch = 0; ch < 8; ch++) {
        __syncthreads();
        #pragma unroll
        for (int i = 0; i < 4; i++) {
            int idx = tid + i * 256;
            int r = idx >> 4, c4 = idx & 15;
            float4 v = *(const float4*)(src + (row0 + r) * DIM + ch * 64 + c4 * 4);
            s[r][c4 * 4 + 0] = v.x; s[r][c4 * 4 + 1] = v.y;
            s[r][c4 * 4 + 2] = v.z; s[r][c4 * 4 + 3] = v.w;
        }
        __syncthreads();
        if (tid < 64) {
            #pragma unroll 16
            for (int c = 0; c < 64; c++) {
                float v = s[tid][c];
                acc = __fadd_rn(acc, __fmul_rn(v, v));
            }
        }
    }
    if (tid < 64) dst[row0 + tid] = fmaxf(__fsqrt_rn(acc), 1e-12f);
}
__global__ __launch_bounds__(256) void res_norm_kernel() {
    seq_norm_block(g_res, g_rnorm, (size_t)blockIdx.x * 64);
}
__global__ __launch_bounds__(256) void cb_all_norm_kernel(const float* __restrict__ cb) {
    seq_norm_block(cb, g_cnorm_all, (size_t)blockIdx.x * 64);
}

// ---------------------------------------------------------------------------
// splits
// ---------------------------------------------------------------------------
__global__ __launch_bounds__(256) void res_split_kernel() {
    size_t g = (size_t)blockIdx.x * 256 + threadIdx.x;
    size_t i = g * 8;
    float n = g_rnorm[i >> 9];
    float4 v0 = *(const float4*)(g_res + i);
    float4 v1 = *(const float4*)(g_res + i + 4);
    uint4 uh;
    uh.x = bf2u(__fdiv_rn(v0.x, n), __fdiv_rn(v0.y, n));
    uh.y = bf2u(__fdiv_rn(v0.z, n), __fdiv_rn(v0.w, n));
    uh.z = bf2u(__fdiv_rn(v1.x, n), __fdiv_rn(v1.y, n));
    uh.w = bf2u(__fdiv_rn(v1.z, n), __fdiv_rn(v1.w, n));
    g_ahi[g] = uh;
}
__global__ __launch_bounds__(256) void cb_all_split_kernel(const float* __restrict__ cb) {
    size_t g = (size_t)blockIdx.x * 256 + threadIdx.x;
    size_t i = g * 8;
    float n = g_cnorm_all[i >> 9];
    float an[8];
    float4 v0 = *(const float4*)(cb + i);
    float4 v1 = *(const float4*)(cb + i + 4);
    an[0] = __fdiv_rn(v0.x, n); an[1] = __fdiv_rn(v0.y, n);
    an[2] = __fdiv_rn(v0.z, n); an[3] = __fdiv_rn(v0.w, n);
    an[4] = __fdiv_rn(v1.x, n); an[5] = __fdiv_rn(v1.y, n);
    an[6] = __fdiv_rn(v1.z, n); an[7] = __fdiv_rn(v1.w, n);
    *(float4*)(g_bnorm_all + i)     = make_float4(an[0], an[1], an[2], an[3]);
    *(float4*)(g_bnorm_all + i + 4) = make_float4(an[4], an[5], an[6], an[7]);
    uint4 uh;
    uh.x = bf2u(an[0], an[1]); uh.y = bf2u(an[2], an[3]);
    uh.z = bf2u(an[4], an[5]); uh.w = bf2u(an[6], an[7]);
    g_bhi_all[g] = uh;
}

// ---------------------------------------------------------------------------
// FAST PASS (round-10 proven GEMM core) + flagging + fused rescore-prep.
// ---------------------------------------------------------------------------
__global__ __launch_bounds__(256, 2) void fast_gemm_kernel(int q) {
    extern __shared__ char smem[];
    const uint32_t sb = smem_u32(smem);
    float* rbest = (float*)(smem + RED_OFF);
    float* rsec  = rbest + 512;
    int*   ridx  = (int*)(rsec + 512);
    __shared__ int s_lrow[128], s_lslot[128];
    __shared__ int s_cnt;

    const int tid  = threadIdx.x;
    const int lane = tid & 31, wid = tid >> 5;
    const int wm = wid >> 2, wn = wid & 3;
    const int g4 = lane >> 2, tig = lane & 3;
    const int row0 = blockIdx.x * BM;

    const __nv_bfloat16* Ahi = (const __nv_bfloat16*)g_ahi;
    const __nv_bfloat16* Bhi = (const __nv_bfloat16*)g_bhi_all + (size_t)q * NK * DIM;

    const int lrow = lane & 15;
    const int lchk = lane >> 4;

    float best[8], sec[8];
    int   bidx[8];
    #pragma unroll
    for (int i = 0; i < 8; i++) { best[i] = -3.4e38f; sec[i] = -3.4e38f; bidx[i] = 0; }

    for (int ct = 0; ct < CTILES; ct++) {
        float acc[4][4][4];
        #pragma unroll
        for (int mf = 0; mf < 4; mf++)
            #pragma unroll
            for (int nf = 0; nf < 4; nf++)
                #pragma unroll
                for (int c = 0; c < 4; c++) acc[mf][nf][c] = 0.f;

        {
            #pragma unroll
            for (int i = 0; i < 4; i++) {
                int idx = tid + i * 256;
                int r = idx >> 3, c16 = idx & 7;
                cp16(sb + SA_OFF + SWZ128(r * 128 + c16 * 16),
                     Ahi + (size_t)(row0 + r) * DIM + c16 * 8);
                cp16(sb + SB_OFF + SWZ128(r * 128 + c16 * 16),
                     Bhi + (size_t)(ct * BN + r) * DIM + c16 * 8);
            }
            CP_COMMIT();
        }

        for (int kc = 0; kc < KCH; kc++) {
            if (kc + 1 < KCH) {
                int st = (kc + 1) & 1;
                int kk = (kc + 1) * BK;
                #pragma unroll
                for (int i = 0; i < 4; i++) {
                    int idx = tid + i * 256;
                    int r = idx >> 3, c16 = idx & 7;
                    cp16(sb + SA_OFF + st * 16384 + SWZ128(r * 128 + c16 * 16),
                         Ahi + (size_t)(row0 + r) * DIM + kk + c16 * 8);
                    cp16(sb + SB_OFF + st * 16384 + SWZ128(r * 128 + c16 * 16),
                         Bhi + (size_t)(ct * BN + r) * DIM + kk + c16 * 8);
                }
                CP_COMMIT();
                CP_WAIT(1);
            } else {
                CP_WAIT(0);
            }
            __syncthreads();

            const uint32_t ab = sb + SA_OFF + (kc & 1) * 16384;
            const uint32_t bb = sb + SB_OFF + (kc & 1) * 16384;

            #pragma unroll
            for (int ks = 0; ks < 4; ks++) {
                const int chk = ks * 2 + lchk;
                unsigned a[4][4];
                #pragma unroll
                for (int mf = 0; mf < 4; mf++) {
                    int r = wm * 64 + mf * 16 + lrow;
                    ldsm4(a[mf], ab + SWZ128(r * 128 + chk * 16));
                }
                unsigned b[2][4];
                #pragma unroll
                for (int nf2 = 0; nf2 < 2; nf2++) {
                    int r = wn * 32 + nf2 * 16 + lrow;
                    ldsm4(b[nf2], bb + SWZ128(r * 128 + chk * 16));
                }
                #pragma unroll
                for (int mf = 0; mf < 4; mf++) {
                    #pragma unroll
                    for (int nf = 0; nf < 4; nf++) {
                        const int n2 = nf >> 1, h = nf & 1;
                        mma16816(acc[mf][nf], a[mf], b[n2][h], b[n2][h + 2]);
                    }
                }
            }
            __syncthreads();
        }

        #pragma unroll
        for (int nf = 0; nf < 4; nf++) {
            int colb = ct * BN + wn * 32 + nf * 8 + tig * 2;
            #pragma unroll
            for (int mf = 0; mf < 4; mf++) {
                #pragma unroll
                for (int h = 0; h < 2; h++) {
                    int slot = mf * 2 + h;
                    float v0 = acc[mf][nf][h * 2 + 0];
                    float v1 = acc[mf][nf][h * 2 + 1];
                    if (v0 > best[slot]) { sec[slot] = best[slot]; best[slot] = v0; bidx[slot] = colb; }
                    else if (v0 > sec[slot]) sec[slot] = v0;
                    if (v1 > best[slot]) { sec[slot] = best[slot]; best[slot] = v1; bidx[slot] = colb + 1; }
                    else if (v1 > sec[slot]) sec[slot] = v1;
                }
            }
        }
    }

    #pragma unroll
    for (int off = 1; off <= 2; off <<= 1) {
        #pragma unroll
        for (int sl = 0; sl < 8; sl++) {
            float ob = __shfl_xor_sync(0xffffffffu, best[sl], off);
            float os = __shfl_xor_sync(0xffffffffu, sec[sl], off);
            int   oi = __shfl_xor_sync(0xffffffffu, bidx[sl], off);
            if (ob > best[sl] || (ob == best[sl] && oi < bidx[sl])) {
                sec[sl] = fmaxf(best[sl], os);
                best[sl] = ob; bidx[sl] = oi;
            } else {
                sec[sl] = fmaxf(sec[sl], ob);
            }
        }
    }

    __syncthreads();
    if (tid == 0) s_cnt = 0;
    if (tig == 0) {
        #pragma unroll
        for (int sl = 0; sl < 8; sl++) {
            int rowl = wm * 64 + (sl >> 1) * 16 + (sl & 1) * 8 + g4;
            rbest[wn * 128 + rowl] = best[sl];
            rsec [wn * 128 + rowl] = sec[sl];
            ridx [wn * 128 + rowl] = bidx[sl];
        }
    }
    __syncthreads();
    if (tid < 128) {
        float b = -3.4e38f, s2 = -3.4e38f; int bi = 0;
        #pragma unroll
        for (int w = 0; w < 4; w++) {
            float wb = rbest[w * 128 + tid], ws = rsec[w * 128 + tid];
            int   wi = ridx[w * 128 + tid];
            if (wb > b || (wb == b && wi < bi)) {
                s2 = fmaxf(b, ws); b = wb; bi = wi;
            } else {
                s2 = fmaxf(s2, wb);
            }
        }
        int row = row0 + tid;
        g_ids[row] = bi;
        if (b - s2 < THRESH) {
            int slot = atomicAdd(&g_flag_count, 1);
            g_flag_rows[slot] = row;
            g_pkey[slot] = 0ull;                 // reset key (replay-safe)
            int l = atomicAdd(&s_cnt, 1);
            s_lrow[l] = tid; s_lslot[l] = slot;
        }
    }
    __syncthreads();

    // fused rescore-prep: cooperatively write normalized flagged rows
    const int cnt = s_cnt;
    for (int e = 0; e < cnt; e++) {
        int row = row0 + s_lrow[e];
        float n = g_rnorm[row];
        const float* src = g_res + (size_t)row * DIM;
        float* dst = g_aflag + (size_t)s_lslot[e] * DIM;
        for (int i = tid * 4; i < DIM; i += 1024) {
            float4 v = *(const float4*)(src + i);
            float4 o;
            o.x = __fdiv_rn(v.x, n); o.y = __fdiv_rn(v.y, n);
            o.z = __fdiv_rn(v.z, n); o.w = __fdiv_rn(v.w, n);
            *(float4*)(dst + i) = o;
        }
    }
}

// ---------------------------------------------------------------------------
// EXACT RESCORE (bit-exact FFMA2), 8-way column-sliced; merges via atomicMax
// on packed (sim, ~idx) keys — exact argmax-with-lowest-index semantics.
// ---------------------------------------------------------------------------
__global__ __launch_bounds__(256) void rescore_kernel(int q) {
    const int count = g_flag_count;
    const int base  = blockIdx.x * 128;
    if (base >= count) return;
    const int slice = blockIdx.y;
    const int cs0   = slice * 512;
    const float* Bn = g_bnorm_all + (size_t)q * NK * DIM;

    __shared__ float As[32][130];
    __shared__ float Bs[32][130];

    const int tid = threadIdx.x;
    const int tx  = tid & 15;
    const int ty  = tid >> 4;

    float best[8];
    int   bidx[8];
    #pragma unroll
    for (int r = 0; r < 8; r++) { best[r] = -3.4e38f; bidx[r] = 0; }

    for (int ct = cs0; ct < cs0 + 512; ct += 128) {
        unsigned long long accp[8][4];
        #pragma unroll
        for (int r = 0; r < 8; r++)
            #pragma unroll
            for (int j = 0; j < 4; j++) accp[r][j] = 0ull;

        for (int kk = 0; kk < DIM; kk += 32) {
            __syncthreads();
            #pragma unroll
            for (int t = 0; t < 4; t++) {
                int f = tid + t * 256;
                int r = f >> 3;
                int c = (f & 7) << 2;
                int slot = base + r;
                if (slot >= count) slot = 0;
                float4 va = *(const float4*)(g_aflag + (size_t)slot * DIM + kk + c);
                As[c + 0][r] = va.x; As[c + 1][r] = va.y;
                As[c + 2][r] = va.z; As[c + 3][r] = va.w;
                float4 vb = *(const float4*)(Bn + (size_t)(ct + r) * DIM + kk + c);
                Bs[c + 0][r] = vb.x; Bs[c + 1][r] = vb.y;
                Bs[c + 2][r] = vb.z; Bs[c + 3][r] = vb.w;
            }
            __syncthreads();

            #pragma unroll
            for (int k = 0; k < 32; k++) {
                unsigned long long bp[4];
                #pragma unroll
                for (int j = 0; j < 4; j++) {
                    float2 b2 = *(const float2*)&Bs[k][2 * tx + 32 * j];
                    bp[j] = packf2(b2.x, b2.y);
                }
                #pragma unroll
                for (int i = 0; i < 4; i++) {
                    float2 a2 = *(const float2*)&As[k][2 * ty + 32 * i];
                    unsigned long long ap0 = packf2(a2.x, a2.x);
                    unsigned long long ap1 = packf2(a2.y, a2.y);
                    #pragma unroll
                    for (int j = 0; j < 4; j++) {
                        fmaf2(accp[2 * i + 0][j], ap0, bp[j]);
                        fmaf2(accp[2 * i + 1][j], ap1, bp[j]);
                    }
                }
            }
        }

        #pragma unroll
        for (int j = 0; j < 4; j++) {
            int c0 = ct + 2 * tx + 32 * j;
            #pragma unroll
            for (int r = 0; r < 8; r++) {
                float v0, v1;
                unpackf2(accp[r][j], v0, v1);
                if (v0 > best[r]) { best[r] = v0; bidx[r] = c0; }
                if (v1 > best[r]) { best[r] = v1; bidx[r] = c0 + 1; }
            }
        }
    }

    #pragma unroll
    for (int off = 8; off; off >>= 1) {
        #pragma unroll
        for (int r = 0; r < 8; r++) {
            float ov = __shfl_xor_sync(0xffffffffu, best[r], off);
            int   oi = __shfl_xor_sync(0xffffffffu, bidx[r], off);
            if (ov > best[r] || (ov == best[r] && oi < bidx[r])) {
                best[r] = ov; bidx[r] = oi;
            }
        }
    }
    if (tx == 0) {
        #pragma unroll
        for (int r = 0; r < 8; r++) {
            int slot = base + 2 * ty + 32 * (r >> 1) + (r & 1);
            if (slot < count)
                atomicMax(&g_pkey[slot], mkkey(best[r], bidx[r]));
        }
    }
}

// apply: decode winning key -> id for flagged rows
__global__ __launch_bounds__(128) void apply_kernel() {
    int t = blockIdx.x * 128 + threadIdx.x;
    if (t >= g_flag_count) return;
    unsigned long long key = g_pkey[t];
    g_ids[g_flag_rows[t]] = (int)(~(unsigned)(key & 0xffffffffu));
}

// ---------------------------------------------------------------------------
// FUSED: residual update + hard accumulate + new-res norm + bf16 split.
// ---------------------------------------------------------------------------
__global__ __launch_bounds__(256) void update_norm_split_kernel(
        const float* __restrict__ cbq, float* __restrict__ hard,
        float* __restrict__ out_ids, int q) {
    __shared__ float s[64][65];
    __shared__ int   sid[64];
    __shared__ float snorm[64];
    const int tid  = threadIdx.x;
    const size_t row0 = (size_t)blockIdx.x * 64;

    if (blockIdx.x == 0 && tid == 0) g_flag_count = 0;
    if (tid < 64) {
        int id = g_ids[row0 + tid];
        sid[tid] = id;
        if (out_ids != nullptr)
            out_ids[(row0 + tid) * NQ + q] = (float)id;
    }
    __syncthreads();

    float acc = 0.f;
    for (int ch = 0; ch < 8; ch++) {
        #pragma unroll
        for (int i = 0; i < 4; i++) {
            int idx = tid + i * 256;
            int r = idx >> 4, c4 = idx & 15;
            size_t off = (row0 + r) * DIM + ch * 64 + c4 * 4;
            float4 rv = *(const float4*)(g_res + off);
            float4 cv = *(const float4*)(cbq + (size_t)sid[r] * DIM + ch * 64 + c4 * 4);
            float4 nr;
            nr.x = __fsub_rn(rv.x, cv.x); nr.y = __fsub_rn(rv.y, cv.y);
            nr.z = __fsub_rn(rv.z, cv.z); nr.w = __fsub_rn(rv.w, cv.w);
            *(float4*)(g_res + off) = nr;
            float4 hv = *(const float4*)(hard + off);
            hv.x = __fadd_rn(hv.x, cv.x); hv.y = __fadd_rn(hv.y, cv.y);
            hv.z = __fadd_rn(hv.z, cv.z); hv.w = __fadd_rn(hv.w, cv.w);
            *(float4*)(hard + off) = hv;
            s[r][c4 * 4 + 0] = nr.x; s[r][c4 * 4 + 1] = nr.y;
            s[r][c4 * 4 + 2] = nr.z; s[r][c4 * 4 + 3] = nr.w;
        }
        __syncthreads();
        if (tid < 64) {
            #pragma unroll 16
            for (int c = 0; c < 64; c++) {
                float v = s[tid][c];
                acc = __fadd_rn(acc, __fmul_rn(v, v));
            }
        }
        __syncthreads();
    }
    if (tid < 64) {
        float n = fmaxf(__fsqrt_rn(acc), 1e-12f);
        g_rnorm[row0 + tid] = n;
        snorm[tid] = n;
    }
    __syncthreads();

    #pragma unroll
    for (int it = 0; it < 16; it++) {
        int gl = tid + it * 256;
        int r  = gl >> 6;
        float n = snorm[r];
        size_t i = row0 * DIM + (size_t)gl * 8;
        float4 v0 = *(const float4*)(g_res + i);
        float4 v1 = *(const float4*)(g_res + i + 4);
        uint4 uh;
        uh.x = bf2u(__fdiv_rn(v0.x, n), __fdiv_rn(v0.y, n));
        uh.y = bf2u(__fdiv_rn(v0.z, n), __fdiv_rn(v0.w, n));
        uh.z = bf2u(__fdiv_rn(v1.x, n), __fdiv_rn(v1.y, n));
        uh.w = bf2u(__fdiv_rn(v1.z, n), __fdiv_rn(v1.w, n));
        g_ahi[i / 8] = uh;
    }
}

// ---------------------------------------------------------------------------
extern "C" void kernel_launch(void* const* d_in, const int* in_sizes, int n_in,
                              void* d_out, int out_size) {
    const float* x  = (const float*)d_in[0];
    const float* cb = (const float*)d_in[1];
    float* out      = (float*)d_out;

    cudaFuncSetAttribute(fast_gemm_kernel,
                         cudaFuncAttributeMaxDynamicSharedMemorySize, SMEM_FAST);

    const size_t nd = (size_t)N_ROWS * DIM;
    float* out_ids  = ((size_t)out_size >= nd + (size_t)N_ROWS * NQ)
                      ? out + nd : nullptr;

    init_kernel<<<N_ROWS * DIM / 1024, 256>>>(x, out);
    res_norm_kernel<<<N_ROWS / 64, 256>>>();
    res_split_kernel<<<N_ROWS * DIM / 8 / 256, 256>>>();
    cb_all_norm_kernel<<<NQ * NK / 64, 256>>>(cb);
    cb_all_split_kernel<<<(size_t)NQ * NK * DIM / 8 / 256, 256>>>(cb);

    for (int q = 0; q < NQ; q++) {
        const float* cbq = cb + (size_t)q * NK * DIM;
        fast_gemm_kernel<<<N_ROWS / BM, 256, SMEM_FAST>>>(q);
        rescore_kernel<<<dim3(N_ROWS / 128, 8), 256>>>(q);
        apply_kernel<<<N_ROWS / 128, 128>>>();
        update_norm_split_kernel<<<N_ROWS / 64, 256>>>(cbq, out, out_ids, q);
    }
}

// round 15
// speedup vs baseline: 1.2013x; 1.2013x over previous
#include <cuda_runtime.h>
#include <cuda_fp16.h>
#include <cstdint>
#include <math.h>

#define N_ROWS 32768
#define DIM    512
#define NQ     8
#define NK     4096
#define THRESH 1e-4f

// fast kernel geometry (round-10 proven, FROZEN)
#define BM 128
#define BN 128
#define BK 64
#define CTILES (NK / BN)   // 32
#define KCH    (DIM / BK)  // 8

#define SA_OFF   0
#define SB_OFF   32768
#define RED_OFF  65536
#define SMEM_FAST (65536 + 512 * 4 * 3)  // 71680

// Scratch (__device__ globals, referenced by name in kernels only)
__device__ float g_res[(size_t)N_ROWS * DIM];
__device__ float g_bnorm_all[(size_t)NQ * NK * DIM];   // normalized codebooks, fp32
__device__ float g_rnorm[N_ROWS];
__device__ float g_cnorm_all[NQ * NK];
__device__ int   g_ids[N_ROWS];
__device__ int   g_flag_count;
__device__ int   g_flag_rows[N_ROWS];
__device__ uint4 g_ahi[(size_t)N_ROWS * DIM / 8];           // fp16 residual
__device__ uint4 g_bhi_all[(size_t)NQ * NK * DIM / 8];      // fp16 codebooks
__device__ float g_aflag[(size_t)N_ROWS * DIM];             // normalized flagged rows
__device__ float g_pbest[(size_t)N_ROWS * 8];
__device__ int   g_pidx[(size_t)N_ROWS * 8];

// ---------------------------------------------------------------------------
// helpers
// ---------------------------------------------------------------------------
__device__ __forceinline__ uint32_t smem_u32(const void* p) {
    uint32_t a;
    asm("{ .reg .u64 t; cvta.to.shared.u64 t, %1; cvt.u32.u64 %0, t; }"
        : "=r"(a) : "l"(p));
    return a;
}
__device__ __forceinline__ unsigned long long packf2(float lo, float hi) {
    unsigned long long r;
    asm("mov.b64 %0, {%1, %2};" : "=l"(r) : "f"(lo), "f"(hi));
    return r;
}
__device__ __forceinline__ void fmaf2(unsigned long long& d,
                                      unsigned long long a, unsigned long long b) {
    asm("fma.rn.f32x2 %0, %1, %2, %0;" : "+l"(d) : "l"(a), "l"(b));
}
__device__ __forceinline__ void unpackf2(unsigned long long p, float& lo, float& hi) {
    asm("mov.b64 {%0, %1}, %2;" : "=f"(lo), "=f"(hi) : "l"(p));
}
__device__ __forceinline__ unsigned h2u(float x, float y) {   // x -> low 16 bits
    __half2 v = __floats2half2_rn(x, y);
    return *(unsigned*)&v;
}
__device__ __forceinline__ void cp16(uint32_t dst, const void* src) {
    asm volatile("cp.async.cg.shared.global [%0], [%1], 16;"
                 :: "r"(dst), "l"(src));
}
#define CP_COMMIT() asm volatile("cp.async.commit_group;" ::: "memory")
#define CP_WAIT(n)  asm volatile("cp.async.wait_group %0;" :: "n"(n) : "memory")
__device__ __forceinline__ void ldsm4(unsigned r[4], uint32_t addr) {
    asm volatile("ldmatrix.sync.aligned.m8n8.x4.shared.b16 {%0,%1,%2,%3}, [%4];"
                 : "=r"(r[0]), "=r"(r[1]), "=r"(r[2]), "=r"(r[3]) : "r"(addr));
}
__device__ __forceinline__ void mma16816(float c[4], const unsigned a[4],
                                         unsigned b0, unsigned b1) {
    asm volatile(
        "mma.sync.aligned.m16n8k16.row.col.f32.f16.f16.f32 "
        "{%0,%1,%2,%3}, {%4,%5,%6,%7}, {%8,%9}, {%0,%1,%2,%3};"
        : "+f"(c[0]), "+f"(c[1]), "+f"(c[2]), "+f"(c[3])
        : "r"(a[0]), "r"(a[1]), "r"(a[2]), "r"(a[3]), "r"(b0), "r"(b1));
}
#define SWZ128(bo) ((bo) ^ (((bo) >> 3) & 0x70))

// ---------------------------------------------------------------------------
// init: res = x, hard = 0
// ---------------------------------------------------------------------------
__global__ __launch_bounds__(256) void init_kernel(const float* __restrict__ x,
                                                   float* __restrict__ hard) {
    if (blockIdx.x == 0 && threadIdx.x == 0) g_flag_count = 0;
    size_t i = ((size_t)blockIdx.x * 256 + threadIdx.x) * 4;
    float4 v = *(const float4*)(x + i);
    *(float4*)(g_res + i) = v;
    *(float4*)(hard + i) = make_float4(0.f, 0.f, 0.f, 0.f);
}

// ---------------------------------------------------------------------------
// Row L2 norm, STRICT SEQUENTIAL fp32 order, coalesced via smem staging.
// ---------------------------------------------------------------------------
__device__ __forceinline__ void seq_norm_block(const float* __restrict__ src,
                                               float* __restrict__ dst,
                                               size_t row0) {
    __shared__ float s[64][65];
    const int tid = threadIdx.x;
    float acc = 0.f;
    for (int ch = 0; ch < 8; ch++) {
        __syncthreads();
        #pragma unroll
        for (int i = 0; i < 4; i++) {
            int idx = tid + i * 256;
            int r = idx >> 4, c4 = idx & 15;
            float4 v = *(const float4*)(src + (row0 + r) * DIM + ch * 64 + c4 * 4);
            s[r][c4 * 4 + 0] = v.x; s[r][c4 * 4 + 1] = v.y;
            s[r][c4 * 4 + 2] = v.z; s[r][c4 * 4 + 3] = v.w;
        }
        __syncthreads();
        if (tid < 64) {
            #pragma unroll 16
            for (int c = 0; c < 64; c++) {
                float v = s[tid][c];
                acc = __fadd_rn(acc, __fmul_rn(v, v));
            }
        }
    }
    if (tid < 64) dst[row0 + tid] = fmaxf(__fsqrt_rn(acc), 1e-12f);
}
__global__ __launch_bounds__(256) void res_norm_kernel() {
    seq_norm_block(g_res, g_rnorm, (size_t)blockIdx.x * 64);
}
__global__ __launch_bounds__(256) void cb_all_norm_kernel(const float* __restrict__ cb) {
    seq_norm_block(cb, g_cnorm_all, (size_t)blockIdx.x * 64);
}

// ---------------------------------------------------------------------------
// splits: res -> fp16; cb -> fp32 normalized + fp16
// ---------------------------------------------------------------------------
__global__ __launch_bounds__(256) void res_split_kernel() {
    size_t g = (size_t)blockIdx.x * 256 + threadIdx.x;
    size_t i = g * 8;
    float n = g_rnorm[i >> 9];
    float4 v0 = *(const float4*)(g_res + i);
    float4 v1 = *(const float4*)(g_res + i + 4);
    uint4 uh;
    uh.x = h2u(__fdiv_rn(v0.x, n), __fdiv_rn(v0.y, n));
    uh.y = h2u(__fdiv_rn(v0.z, n), __fdiv_rn(v0.w, n));
    uh.z = h2u(__fdiv_rn(v1.x, n), __fdiv_rn(v1.y, n));
    uh.w = h2u(__fdiv_rn(v1.z, n), __fdiv_rn(v1.w, n));
    g_ahi[g] = uh;
}
__global__ __launch_bounds__(256) void cb_all_split_kernel(const float* __restrict__ cb) {
    size_t g = (size_t)blockIdx.x * 256 + threadIdx.x;
    size_t i = g * 8;
    float n = g_cnorm_all[i >> 9];
    float an[8];
    float4 v0 = *(const float4*)(cb + i);
    float4 v1 = *(const float4*)(cb + i + 4);
    an[0] = __fdiv_rn(v0.x, n); an[1] = __fdiv_rn(v0.y, n);
    an[2] = __fdiv_rn(v0.z, n); an[3] = __fdiv_rn(v0.w, n);
    an[4] = __fdiv_rn(v1.x, n); an[5] = __fdiv_rn(v1.y, n);
    an[6] = __fdiv_rn(v1.z, n); an[7] = __fdiv_rn(v1.w, n);
    *(float4*)(g_bnorm_all + i)     = make_float4(an[0], an[1], an[2], an[3]);
    *(float4*)(g_bnorm_all + i + 4) = make_float4(an[4], an[5], an[6], an[7]);
    uint4 uh;
    uh.x = h2u(an[0], an[1]); uh.y = h2u(an[2], an[3]);
    uh.z = h2u(an[4], an[5]); uh.w = h2u(an[6], an[7]);
    g_bhi_all[g] = uh;
}

// ---------------------------------------------------------------------------
// FAST PASS (round-10 proven, FROZEN; fp16 operands)
// ---------------------------------------------------------------------------
__global__ __launch_bounds__(256, 2) void fast_gemm_kernel(int q) {
    extern __shared__ char smem[];
    const uint32_t sb = smem_u32(smem);
    float* rbest = (float*)(smem + RED_OFF);
    float* rsec  = rbest + 512;
    int*   ridx  = (int*)(rsec + 512);

    const int tid  = threadIdx.x;
    const int lane = tid & 31, wid = tid >> 5;
    const int wm = wid >> 2, wn = wid & 3;
    const int g4 = lane >> 2, tig = lane & 3;
    const int row0 = blockIdx.x * BM;

    const __half* Ahi = (const __half*)g_ahi;
    const __half* Bhi = (const __half*)g_bhi_all + (size_t)q * NK * DIM;

    const int lrow = lane & 15;
    const int lchk = lane >> 4;

    float best[8], sec[8];
    int   bidx[8];
    #pragma unroll
    for (int i = 0; i < 8; i++) { best[i] = -3.4e38f; sec[i] = -3.4e38f; bidx[i] = 0; }

    for (int ct = 0; ct < CTILES; ct++) {
        float acc[4][4][4];
        #pragma unroll
        for (int mf = 0; mf < 4; mf++)
            #pragma unroll
            for (int nf = 0; nf < 4; nf++)
                #pragma unroll
                for (int c = 0; c < 4; c++) acc[mf][nf][c] = 0.f;

        {
            #pragma unroll
            for (int i = 0; i < 4; i++) {
                int idx = tid + i * 256;
                int r = idx >> 3, c16 = idx & 7;
                cp16(sb + SA_OFF + SWZ128(r * 128 + c16 * 16),
                     Ahi + (size_t)(row0 + r) * DIM + c16 * 8);
                cp16(sb + SB_OFF + SWZ128(r * 128 + c16 * 16),
                     Bhi + (size_t)(ct * BN + r) * DIM + c16 * 8);
            }
            CP_COMMIT();
        }

        for (int kc = 0; kc < KCH; kc++) {
            if (kc + 1 < KCH) {
                int st = (kc + 1) & 1;
                int kk = (kc + 1) * BK;
                #pragma unroll
                for (int i = 0; i < 4; i++) {
                    int idx = tid + i * 256;
                    int r = idx >> 3, c16 = idx & 7;
                    cp16(sb + SA_OFF + st * 16384 + SWZ128(r * 128 + c16 * 16),
                         Ahi + (size_t)(row0 + r) * DIM + kk + c16 * 8);
                    cp16(sb + SB_OFF + st * 16384 + SWZ128(r * 128 + c16 * 16),
                         Bhi + (size_t)(ct * BN + r) * DIM + kk + c16 * 8);
                }
                CP_COMMIT();
                CP_WAIT(1);
            } else {
                CP_WAIT(0);
            }
            __syncthreads();

            const uint32_t ab = sb + SA_OFF + (kc & 1) * 16384;
            const uint32_t bb = sb + SB_OFF + (kc & 1) * 16384;

            #pragma unroll
            for (int ks = 0; ks < 4; ks++) {
                const int chk = ks * 2 + lchk;
                unsigned a[4][4];
                #pragma unroll
                for (int mf = 0; mf < 4; mf++) {
                    int r = wm * 64 + mf * 16 + lrow;
                    ldsm4(a[mf], ab + SWZ128(r * 128 + chk * 16));
                }
                unsigned b[2][4];
                #pragma unroll
                for (int nf2 = 0; nf2 < 2; nf2++) {
                    int r = wn * 32 + nf2 * 16 + lrow;
                    ldsm4(b[nf2], bb + SWZ128(r * 128 + chk * 16));
                }
                #pragma unroll
                for (int mf = 0; mf < 4; mf++) {
                    #pragma unroll
                    for (int nf = 0; nf < 4; nf++) {
                        const int n2 = nf >> 1, h = nf & 1;
                        mma16816(acc[mf][nf], a[mf], b[n2][h], b[n2][h + 2]);
                    }
                }
            }
            __syncthreads();
        }

        #pragma unroll
        for (int nf = 0; nf < 4; nf++) {
            int colb = ct * BN + wn * 32 + nf * 8 + tig * 2;
            #pragma unroll
            for (int mf = 0; mf < 4; mf++) {
                #pragma unroll
                for (int h = 0; h < 2; h++) {
                    int slot = mf * 2 + h;
                    float v0 = acc[mf][nf][h * 2 + 0];
                    float v1 = acc[mf][nf][h * 2 + 1];
                    if (v0 > best[slot]) { sec[slot] = best[slot]; best[slot] = v0; bidx[slot] = colb; }
                    else if (v0 > sec[slot]) sec[slot] = v0;
                    if (v1 > best[slot]) { sec[slot] = best[slot]; best[slot] = v1; bidx[slot] = colb + 1; }
                    else if (v1 > sec[slot]) sec[slot] = v1;
                }
            }
        }
    }

    #pragma unroll
    for (int off = 1; off <= 2; off <<= 1) {
        #pragma unroll
        for (int sl = 0; sl < 8; sl++) {
            float ob = __shfl_xor_sync(0xffffffffu, best[sl], off);
            float os = __shfl_xor_sync(0xffffffffu, sec[sl], off);
            int   oi = __shfl_xor_sync(0xffffffffu, bidx[sl], off);
            if (ob > best[sl] || (ob == best[sl] && oi < bidx[sl])) {
                sec[sl] = fmaxf(best[sl], os);
                best[sl] = ob; bidx[sl] = oi;
            } else {
                sec[sl] = fmaxf(sec[sl], ob);
            }
        }
    }

    __syncthreads();
    if (tig == 0) {
        #pragma unroll
        for (int sl = 0; sl < 8; sl++) {
            int rowl = wm * 64 + (sl >> 1) * 16 + (sl & 1) * 8 + g4;
            rbest[wn * 128 + rowl] = best[sl];
            rsec [wn * 128 + rowl] = sec[sl];
            ridx [wn * 128 + rowl] = bidx[sl];
        }
    }
    __syncthreads();
    if (tid < 128) {
        float b = -3.4e38f, s2 = -3.4e38f; int bi = 0;
        #pragma unroll
        for (int w = 0; w < 4; w++) {
            float wb = rbest[w * 128 + tid], ws = rsec[w * 128 + tid];
            int   wi = ridx[w * 128 + tid];
            if (wb > b || (wb == b && wi < bi)) {
                s2 = fmaxf(b, ws); b = wb; bi = wi;
            } else {
                s2 = fmaxf(s2, wb);
            }
        }
        int row = row0 + tid;
        g_ids[row] = bi;
        if (b - s2 < THRESH) {
            int slot = atomicAdd(&g_flag_count, 1);
            g_flag_rows[slot] = row;
        }
    }
}

// ---------------------------------------------------------------------------
// rescore prep: materialize normalized flagged rows once
// ---------------------------------------------------------------------------
__global__ __launch_bounds__(256) void rescore_prep_kernel() {
    const int count = g_flag_count;
    for (int t = blockIdx.x; t < count; t += gridDim.x) {
        int row = g_flag_rows[t];
        float n = g_rnorm[row];
        const float* src = g_res + (size_t)row * DIM;
        float* dst = g_aflag + (size_t)t * DIM;
        for (int i = threadIdx.x * 4; i < DIM; i += 1024) {
            float4 v = *(const float4*)(src + i);
            float4 o;
            o.x = __fdiv_rn(v.x, n); o.y = __fdiv_rn(v.y, n);
            o.z = __fdiv_rn(v.z, n); o.w = __fdiv_rn(v.w, n);
            *(float4*)(dst + i) = o;
        }
    }
}

// ---------------------------------------------------------------------------
// EXACT RESCORE (bit-exact FFMA2), 8-way column-sliced; reads g_aflag
// ---------------------------------------------------------------------------
__global__ __launch_bounds__(256) void rescore_kernel(int q) {
    const int count = g_flag_count;
    const int base  = blockIdx.x * 128;
    if (base >= count) return;
    const int slice = blockIdx.y;
    const int cs0   = slice * 512;
    const float* Bn = g_bnorm_all + (size_t)q * NK * DIM;

    __shared__ float As[32][130];
    __shared__ float Bs[32][130];

    const int tid = threadIdx.x;
    const int tx  = tid & 15;
    const int ty  = tid >> 4;

    float best[8];
    int   bidx[8];
    #pragma unroll
    for (int r = 0; r < 8; r++) { best[r] = -3.4e38f; bidx[r] = 0; }

    for (int ct = cs0; ct < cs0 + 512; ct += 128) {
        unsigned long long accp[8][4];
        #pragma unroll
        for (int r = 0; r < 8; r++)
            #pragma unroll
            for (int j = 0; j < 4; j++) accp[r][j] = 0ull;

        for (int kk = 0; kk < DIM; kk += 32) {
            __syncthreads();
            #pragma unroll
            for (int t = 0; t < 4; t++) {
                int f = tid + t * 256;
                int r = f >> 3;
                int c = (f & 7) << 2;
                int slot = base + r;
                if (slot >= count) slot = 0;
                float4 va = *(const float4*)(g_aflag + (size_t)slot * DIM + kk + c);
                As[c + 0][r] = va.x; As[c + 1][r] = va.y;
                As[c + 2][r] = va.z; As[c + 3][r] = va.w;
                float4 vb = *(const float4*)(Bn + (size_t)(ct + r) * DIM + kk + c);
                Bs[c + 0][r] = vb.x; Bs[c + 1][r] = vb.y;
                Bs[c + 2][r] = vb.z; Bs[c + 3][r] = vb.w;
            }
            __syncthreads();

            #pragma unroll
            for (int k = 0; k < 32; k++) {
                unsigned long long bp[4];
                #pragma unroll
                for (int j = 0; j < 4; j++) {
                    float2 b2 = *(const float2*)&Bs[k][2 * tx + 32 * j];
                    bp[j] = packf2(b2.x, b2.y);
                }
                #pragma unroll
                for (int i = 0; i < 4; i++) {
                    float2 a2 = *(const float2*)&As[k][2 * ty + 32 * i];
                    unsigned long long ap0 = packf2(a2.x, a2.x);
                    unsigned long long ap1 = packf2(a2.y, a2.y);
                    #pragma unroll
                    for (int j = 0; j < 4; j++) {
                        fmaf2(accp[2 * i + 0][j], ap0, bp[j]);
                        fmaf2(accp[2 * i + 1][j], ap1, bp[j]);
                    }
                }
            }
        }

        #pragma unroll
        for (int j = 0; j < 4; j++) {
            int c0 = ct + 2 * tx + 32 * j;
            #pragma unroll
            for (int r = 0; r < 8; r++) {
                float v0, v1;
                unpackf2(accp[r][j], v0, v1);
                if (v0 > best[r]) { best[r] = v0; bidx[r] = c0; }
                if (v1 > best[r]) { best[r] = v1; bidx[r] = c0 + 1; }
            }
        }
    }

    #pragma unroll
    for (int off = 8; off; off >>= 1) {
        #pragma unroll
        for (int r = 0; r < 8; r++) {
            float ov = __shfl_xor_sync(0xffffffffu, best[r], off);
            int   oi = __shfl_xor_sync(0xffffffffu, bidx[r], off);
            if (ov > best[r] || (ov == best[r] && oi < bidx[r])) {
                best[r] = ov; bidx[r] = oi;
            }
        }
    }
    if (tx == 0) {
        #pragma unroll
        for (int r = 0; r < 8; r++) {
            int slot = base + 2 * ty + 32 * (r >> 1) + (r & 1);
            if (slot < count) {
                g_pbest[(size_t)slot * 8 + slice] = best[r];
                g_pidx[(size_t)slot * 8 + slice]  = bidx[r];
            }
        }
    }
}

__global__ __launch_bounds__(128) void merge_kernel() {
    int t = blockIdx.x * 128 + threadIdx.x;
    if (t >= g_flag_count) return;
    float b = -3.4e38f; int bi = 0;
    #pragma unroll
    for (int j = 0; j < 8; j++) {          // slices ascending = cols ascending
        float pb = g_pbest[(size_t)t * 8 + j];
        if (pb > b) { b = pb; bi = g_pidx[(size_t)t * 8 + j]; }
    }
    g_ids[g_flag_rows[t]] = bi;
}

// ---------------------------------------------------------------------------
// FUSED: residual update + hard accumulate + new-res norm + fp16 split.
// ---------------------------------------------------------------------------
__global__ __launch_bounds__(256) void update_norm_split_kernel(
        const float* __restrict__ cbq, float* __restrict__ hard,
        float* __restrict__ out_ids, int q) {
    __shared__ float s[64][65];
    __shared__ int   sid[64];
    __shared__ float snorm[64];
    const int tid  = threadIdx.x;
    const size_t row0 = (size_t)blockIdx.x * 64;

    if (blockIdx.x == 0 && tid == 0) g_flag_count = 0;
    if (tid < 64) {
        int id = g_ids[row0 + tid];
        sid[tid] = id;
        if (out_ids != nullptr)
            out_ids[(row0 + tid) * NQ + q] = (float)id;
    }
    __syncthreads();

    float acc = 0.f;
    for (int ch = 0; ch < 8; ch++) {
        #pragma unroll
        for (int i = 0; i < 4; i++) {
            int idx = tid + i * 256;
            int r = idx >> 4, c4 = idx & 15;
            size_t off = (row0 + r) * DIM + ch * 64 + c4 * 4;
            float4 rv = *(const float4*)(g_res + off);
            float4 cv = *(const float4*)(cbq + (size_t)sid[r] * DIM + ch * 64 + c4 * 4);
            float4 nr;
            nr.x = __fsub_rn(rv.x, cv.x); nr.y = __fsub_rn(rv.y, cv.y);
            nr.z = __fsub_rn(rv.z, cv.z); nr.w = __fsub_rn(rv.w, cv.w);
            *(float4*)(g_res + off) = nr;
            float4 hv = *(const float4*)(hard + off);
            hv.x = __fadd_rn(hv.x, cv.x); hv.y = __fadd_rn(hv.y, cv.y);
            hv.z = __fadd_rn(hv.z, cv.z); hv.w = __fadd_rn(hv.w, cv.w);
            *(float4*)(hard + off) = hv;
            s[r][c4 * 4 + 0] = nr.x; s[r][c4 * 4 + 1] = nr.y;
            s[r][c4 * 4 + 2] = nr.z; s[r][c4 * 4 + 3] = nr.w;
        }
        __syncthreads();
        if (tid < 64) {
            #pragma unroll 16
            for (int c = 0; c < 64; c++) {
                float v = s[tid][c];
                acc = __fadd_rn(acc, __fmul_rn(v, v));
            }
        }
        __syncthreads();
    }
    if (tid < 64) {
        float n = fmaxf(__fsqrt_rn(acc), 1e-12f);
        g_rnorm[row0 + tid] = n;
        snorm[tid] = n;
    }
    __syncthreads();

    // split pass: updated res (L2-hot) -> fp16
    #pragma unroll
    for (int it = 0; it < 16; it++) {
        int gl = tid + it * 256;
        int r  = gl >> 6;
        float n = snorm[r];
        size_t i = row0 * DIM + (size_t)gl * 8;
        float4 v0 = *(const float4*)(g_res + i);
        float4 v1 = *(const float4*)(g_res + i + 4);
        uint4 uh;
        uh.x = h2u(__fdiv_rn(v0.x, n), __fdiv_rn(v0.y, n));
        uh.y = h2u(__fdiv_rn(v0.z, n), __fdiv_rn(v0.w, n));
        uh.z = h2u(__fdiv_rn(v1.x, n), __fdiv_rn(v1.y, n));
        uh.w = h2u(__fdiv_rn(v1.z, n), __fdiv_rn(v1.w, n));
        g_ahi[i / 8] = uh;
    }
}

// ---------------------------------------------------------------------------
extern "C" void kernel_launch(void* const* d_in, const int* in_sizes, int n_in,
                              void* d_out, int out_size) {
    const float* x  = (const float*)d_in[0];
    const float* cb = (const float*)d_in[1];
    float* out      = (float*)d_out;

    cudaFuncSetAttribute(fast_gemm_kernel,
                         cudaFuncAttributeMaxDynamicSharedMemorySize, SMEM_FAST);

    const size_t nd = (size_t)N_ROWS * DIM;
    float* out_ids  = ((size_t)out_size >= nd + (size_t)N_ROWS * NQ)
                      ? out + nd : nullptr;

    init_kernel<<<N_ROWS * DIM / 1024, 256>>>(x, out);
    res_norm_kernel<<<N_ROWS / 64, 256>>>();
    res_split_kernel<<<N_ROWS * DIM / 8 / 256, 256>>>();
    cb_all_norm_kernel<<<NQ * NK / 64, 256>>>(cb);
    cb_all_split_kernel<<<(size_t)NQ * NK * DIM / 8 / 256, 256>>>(cb);

    for (int q = 0; q < NQ; q++) {
        const float* cbq = cb + (size_t)q * NK * DIM;
        fast_gemm_kernel<<<N_ROWS / BM, 256, SMEM_FAST>>>(q);
        rescore_prep_kernel<<<256, 256>>>();
        rescore_kernel<<<dim3(N_ROWS / 128, 8), 256>>>(q);
        merge_kernel<<<N_ROWS / 128, 128>>>();
        update_norm_split_kernel<<<N_ROWS / 64, 256>>>(cbq, out, out_ids, q);
    }
}